// round 13
// baseline (speedup 1.0000x reference)
#include <cuda_runtime.h>
#include <cuda_fp16.h>
#include <math.h>

#define T_SEQ 8192
#define HID   1024
#define GDIM  2048
#define NCTA  256            // 2 CTAs per SM
#define RECT  128            // 4 warps; warp w owns output cta*4+w for all 3 layers

// tagged hidden state, slice-spread: 4 tagged 8B words per 256B granule
#define GRPW 32                         // 8B words per 256B granule
#define BUFW (256 * GRPW)               // one buffer = 64 KB

// ---------------- static scratch (no allocation) ----------------
__device__ float g_gi[T_SEQ * GDIM];    // layer-0 input projection
__device__ float g_X2[T_SEQ * HID];     // layer-2 outputs
__device__ __align__(256) unsigned long long g_ht[3][2 * BUFW];

__device__ __forceinline__ size_t ht_idx(int word) {
    return (size_t)(word >> 2) * GRPW + (word & 3);
}
__device__ __forceinline__ void st_tagged(unsigned long long* p, float v, unsigned tag) {
    unsigned long long pk = ((unsigned long long)tag << 32) |
                            (unsigned long long)__float_as_uint(v);
    asm volatile("st.global.relaxed.gpu.b64 [%0], %1;" :: "l"(p), "l"(pk) : "memory");
}
#define LDV4(d0,d1,d2,d3,ptr) \
    asm volatile("ld.volatile.global.v4.b32 {%0,%1,%2,%3}, [%4];" \
                 : "=r"(d0),"=r"(d1),"=r"(d2),"=r"(d3) : "l"(ptr))

// packed 2xfp32 FMA (Blackwell f32x2 pipe)
__device__ __forceinline__ unsigned long long ffma2(unsigned long long a,
                                                    unsigned long long b,
                                                    unsigned long long c) {
    unsigned long long d;
    asm("fma.rn.f32x2 %0, %1, %2, %3;" : "=l"(d) : "l"(a), "l"(b), "l"(c));
    return d;
}
__device__ __forceinline__ float hsum2(unsigned long long v) {
    float lo, hi;
    asm("mov.b64 {%0, %1}, %2;" : "=f"(lo), "=f"(hi) : "l"(v));
    return lo + hi;
}
#define UNPK(lo, hi, u) \
    asm("mov.b64 {%0, %1}, %2;" : "=f"(lo), "=f"(hi) : "l"(u))

// try to accept one h vector slice: thread owns granules 2*tid, 2*tid+1
// (words 8*tid..8*tid+7). 4 volatile LDV4s, 8 tag checks, stage on success.
__device__ __forceinline__ bool try_poll(const unsigned long long* base,
                                         unsigned tag, float* st) {
    unsigned a0,a1,a2,a3, b0,b1,b2,b3, c0,c1,c2,c3, e0,e1,e2,e3;
    LDV4(a0,a1,a2,a3, base);            LDV4(b0,b1,b2,b3, base + 2);
    LDV4(c0,c1,c2,c3, base + GRPW);     LDV4(e0,e1,e2,e3, base + GRPW + 2);
    if (a1==tag && a3==tag && b1==tag && b3==tag &&
        c1==tag && c3==tag && e1==tag && e3==tag) {
        st[0]=__uint_as_float(a0); st[1]=__uint_as_float(a2);
        st[2]=__uint_as_float(b0); st[3]=__uint_as_float(b2);
        st[4]=__uint_as_float(c0); st[5]=__uint_as_float(c2);
        st[6]=__uint_as_float(e0); st[7]=__uint_as_float(e2);
        return true;
    }
    return false;
}

// ---------------- init: seed all 3 layers' tagged h ----------------
__global__ void init_all(const float* __restrict__ h0) {
    int i = threadIdx.x;   // 1024 threads
#pragma unroll
    for (int l = 0; l < 3; ++l) {
        g_ht[l][ht_idx(i)] = (unsigned long long)__float_as_uint(h0[l * HID + i]);
        g_ht[l][BUFW + ht_idx(i)] = 0xFFFFFFFF00000000ull;
    }
}

// ---------------- C[M,N] = A[M,K] @ W[N,K]^T + bias[N] ----------------
__global__ __launch_bounds__(256, 2)
void gemm_bias_nt(const float* __restrict__ A, const float* __restrict__ W,
                  const float* __restrict__ bias, float* __restrict__ C,
                  int M, int N, int K) {
    __shared__ float As[8][128];
    __shared__ float Bs[8][128];
    const int tid  = threadIdx.x;
    const int bm   = blockIdx.y * 128;
    const int bn   = blockIdx.x * 128;
    const int lrow = tid >> 1;
    const int lcol = (tid & 1) << 2;
    const int ty   = tid >> 4;
    const int tx   = tid & 15;

    float acc[8][8];
#pragma unroll
    for (int i = 0; i < 8; ++i)
#pragma unroll
        for (int j = 0; j < 8; ++j) acc[i][j] = 0.f;

    const float* Aptr = A + (size_t)(bm + lrow) * K + lcol;
    const float* Wptr = W + (size_t)(bn + lrow) * K + lcol;

    for (int k0 = 0; k0 < K; k0 += 8) {
        float4 av = *(const float4*)(Aptr + k0);
        float4 wv = *(const float4*)(Wptr + k0);
        As[lcol + 0][lrow] = av.x; As[lcol + 1][lrow] = av.y;
        As[lcol + 2][lrow] = av.z; As[lcol + 3][lrow] = av.w;
        Bs[lcol + 0][lrow] = wv.x; Bs[lcol + 1][lrow] = wv.y;
        Bs[lcol + 2][lrow] = wv.z; Bs[lcol + 3][lrow] = wv.w;
        __syncthreads();
#pragma unroll
        for (int k = 0; k < 8; ++k) {
            float4 a0 = *(const float4*)&As[k][ty * 8];
            float4 a1 = *(const float4*)&As[k][ty * 8 + 4];
            float4 b0 = *(const float4*)&Bs[k][tx * 8];
            float4 b1 = *(const float4*)&Bs[k][tx * 8 + 4];
            float ar[8] = {a0.x, a0.y, a0.z, a0.w, a1.x, a1.y, a1.z, a1.w};
            float br[8] = {b0.x, b0.y, b0.z, b0.w, b1.x, b1.y, b1.z, b1.w};
#pragma unroll
            for (int i = 0; i < 8; ++i)
#pragma unroll
                for (int j = 0; j < 8; ++j) acc[i][j] += ar[i] * br[j];
        }
        __syncthreads();
    }

#pragma unroll
    for (int i = 0; i < 8; ++i) {
        int row = bm + ty * 8 + i;
#pragma unroll
        for (int j = 0; j < 8; j += 4) {
            float4 v;
            int col = bn + tx * 8 + j;
            v.x = acc[i][j + 0] + bias[col + 0];
            v.y = acc[i][j + 1] + bias[col + 1];
            v.z = acc[i][j + 2] + bias[col + 2];
            v.w = acc[i][j + 3] + bias[col + 3];
            *(float4*)&C[(size_t)row * N + col] = v;
        }
    }
}

// ---------------- fused 3-layer wavefront MGU, 2 CTAs/SM ----------------
// 256 CTAs x 128 threads (4 warps). Warp w owns output j=cta*4+w of every layer.
// Wavefront step s: layer0 t=s, layer1 t=s-1, layer2 t=s-2.
// Two co-resident CTAs per SM hide each other's rendezvous/reduce latency.
__global__ __launch_bounds__(RECT, 2)
void mgu_fused(const float* __restrict__ w_hh0, const float* __restrict__ w_hh1,
               const float* __restrict__ w_hh2,
               const float* __restrict__ b_hh0, const float* __restrict__ b_hh1,
               const float* __restrict__ b_hh2,
               const float* __restrict__ w_ih1, const float* __restrict__ w_ih2,
               const float* __restrict__ b_ih1, const float* __restrict__ b_ih2,
               const float* __restrict__ gi0, float* __restrict__ X2) {
    extern __shared__ char smraw[];
    __half* swi = (__half*)smraw;                    // [8][256][8] halves (32 KB)
    float*  hs  = (float*)(smraw + 32 * 1024);       // [2][3][1024] fp32 (24 KB)

    const int cta  = blockIdx.x;
    const int tid  = threadIdx.x;
    const int warp = tid >> 5;
    const int lane = tid & 31;
    const int j    = cta * 4 + warp;

    // ---- fill smem gate weights, fp16, f/n interleaved per 4-group ----
    for (int r = 0; r < 4; ++r) {
        int jr = cta * 4 + r;
        const float* f1 = w_ih1 + (size_t)jr * HID;
        const float* n1 = w_ih1 + (size_t)(HID + jr) * HID;
        const float* f2 = w_ih2 + (size_t)jr * HID;
        const float* n2 = w_ih2 + (size_t)(HID + jr) * HID;
        for (int k = tid; k < HID; k += RECT) {
            int g = k >> 2, pos = k & 3;
            size_t b0 = ((size_t)(0 * 4 + r) * 256 + g) * 8;
            size_t b1 = ((size_t)(4 + r) * 256 + g) * 8;
            swi[b0 + pos]     = __float2half(f1[k]);
            swi[b0 + 4 + pos] = __float2half(n1[k]);
            swi[b1 + pos]     = __float2half(f2[k]);
            swi[b1 + 4 + pos] = __float2half(n2[k]);
        }
    }

    // ---- w_hh rows for layers 0,1 as packed pairs ----
    ulonglong2 w0f[8], w0n[8], w1f[8], w1n[8];
#pragma unroll
    for (int i = 0; i < 8; ++i) {
        int col = 4 * (i * 32 + lane);
        w0f[i] = *(const ulonglong2*)&w_hh0[(size_t)j * HID + col];
        w0n[i] = *(const ulonglong2*)&w_hh0[(size_t)(HID + j) * HID + col];
        w1f[i] = *(const ulonglong2*)&w_hh1[(size_t)j * HID + col];
        w1n[i] = *(const ulonglong2*)&w_hh1[(size_t)(HID + j) * HID + col];
    }
    // layer-2 w_hh rows: stream through L1 (112 KB smem/SM -> 116 KB carveout)
    const ulonglong2* w2f_p = (const ulonglong2*)(w_hh2 + (size_t)j * HID);
    const ulonglong2* w2n_p = (const ulonglong2*)(w_hh2 + (size_t)(HID + j) * HID);

    const float bh0f = b_hh0[j], bh0n = b_hh0[HID + j];
    const float bi1f = b_ih1[j], bi1n = b_ih1[HID + j];
    const float bh1f = b_hh1[j], bh1n = b_hh1[HID + j];
    const float bi2f = b_ih2[j], bi2n = b_ih2[HID + j];
    const float bh2f = b_hh2[j], bh2n = b_hh2[HID + j];

    const __half* r1w = swi + (size_t)(0 * 4 + warp) * 256 * 8;
    const __half* r2w = swi + (size_t)(4 + warp) * 256 * 8;

    // hoisted poll bases (per-thread: granules 2*tid, 2*tid+1) and publish slots
    const unsigned long long* b0p = g_ht[0] + (size_t)(2 * tid) * GRPW;
    const unsigned long long* b1p = g_ht[1] + (size_t)(2 * tid) * GRPW;
    const unsigned long long* b2p = g_ht[2] + (size_t)(2 * tid) * GRPW;
    unsigned long long* pub0b = g_ht[0] + ht_idx(j);
    unsigned long long* pub1b = g_ht[1] + ht_idx(j);
    unsigned long long* pub2b = g_ht[2] + ht_idx(j);

    __syncthreads();

    // gi prefetch pipeline: hold step-s values, prefetch s+1 during step s
    float gif0 = 0.f, gin0 = 0.f;
    if (lane == 0) {
        gif0 = __ldcg(&gi0[j]);
        gin0 = __ldcg(&gi0[HID + j]);
    }

    for (int s = 0; s < T_SEQ + 2; ++s) {
        const int p = s & 1, q = p ^ 1;
        const bool act0 = s < T_SEQ;
        const bool act1 = (s >= 1) & (s <= T_SEQ);
        const bool act2 = s >= 2;

        const unsigned long long* p0 = b0p + (p ? BUFW : 0);
        const unsigned long long* p1 = b1p + (q ? BUFW : 0);
        const unsigned long long* p2 = b2p + (p ? BUFW : 0);
        const unsigned tg0 = (unsigned)s, tg1 = (unsigned)(s - 1), tg2 = (unsigned)(s - 2);
        bool d0 = !(s <= T_SEQ), d1 = !(s >= 1), d2 = !(s >= 2);
        float* st0 = hs + (p * 3 + 0) * HID + 8 * tid;
        float* st1 = hs + (p * 3 + 1) * HID + 8 * tid;
        float* st2 = hs + (p * 3 + 2) * HID + 8 * tid;

        // ---- prefetch round: try h1/h2 once before the h0 spin ----
        if (!d1) d1 = try_poll(p1, tg1, st1);
        if (!d2) d2 = try_poll(p2, tg2, st2);

        // ======== rendezvous 1: h0 (drain h1/h2 opportunistically) ========
        while (!d0) {
            d0 = try_poll(p0, tg0, st0);
            if (!d1) d1 = try_poll(p1, tg1, st1);
            if (!d2) d2 = try_poll(p2, tg2, st2);
        }
        __syncthreads();
        const float* h0v = hs + (p * 3 + 0) * HID;

        // A1: w_hh0 dots (packed FMA), keep h0 packed in registers
        ulonglong2 hu[8];
        unsigned long long af0 = 0ull, an0 = 0ull;
#pragma unroll
        for (int i = 0; i < 8; ++i) {
            ulonglong2 h2 = *(const ulonglong2*)&h0v[4 * (i * 32 + lane)];
            hu[i] = h2;
            af0 = ffma2(w0f[i].x, h2.x, af0); af0 = ffma2(w0f[i].y, h2.y, af0);
            an0 = ffma2(w0n[i].x, h2.x, an0); an0 = ffma2(w0n[i].y, h2.y, an0);
        }
        float accf0 = hsum2(af0), accn0 = hsum2(an0);
#pragma unroll
        for (int o = 16; o; o >>= 1) {
            accf0 += __shfl_xor_sync(0xffffffffu, accf0, o);
            accn0 += __shfl_xor_sync(0xffffffffu, accn0, o);
        }
        // publish h0(s+1) EARLY
        if (act0 && lane == 0) {
            float zf = gif0 + accf0 + bh0f;
            zf = fminf(fmaxf(zf, -30.f), 30.f);
            float f = __fdividef(1.f, 1.f + __expf(-zf));
            float z = gin0 + f * (accn0 + bh0n);
            z = fminf(fmaxf(z, -15.f), 15.f);
            float e = __expf(2.f * z);
            float n = 1.f - __fdividef(2.f, e + 1.f);
            float hy = n + (1.f - f) * (h0v[j] - n);
            st_tagged(pub0b + (q ? BUFW : 0), hy, (unsigned)(s + 1));
        }
        if (s + 1 < T_SEQ && lane == 0) {
            gif0 = __ldcg(&gi0[(size_t)(s + 1) * GDIM + j]);
            gin0 = __ldcg(&gi0[(size_t)(s + 1) * GDIM + HID + j]);
        }

        // A2: layer-1 gate dots (interleaved fp16, one LDS.128/iter)
        float g1fv = 0.f, g1nv = 0.f;
#pragma unroll
        for (int i = 0; i < 8; ++i) {
            uint4 wv = *(const uint4*)(r1w + (size_t)(i * 32 + lane) * 8);
            float2 f01 = __half22float2(*(const __half2*)&wv.x);
            float2 f23 = __half22float2(*(const __half2*)&wv.y);
            float2 n01 = __half22float2(*(const __half2*)&wv.z);
            float2 n23 = __half22float2(*(const __half2*)&wv.w);
            float h0f, h1f, h2f, h3f;
            UNPK(h0f, h1f, hu[i].x); UNPK(h2f, h3f, hu[i].y);
            g1fv += f01.x*h0f + f01.y*h1f + f23.x*h2f + f23.y*h3f;
            g1nv += n01.x*h0f + n01.y*h1f + n23.x*h2f + n23.y*h3f;
        }

        // ======== rendezvous 2: h1 AND h2 together ========
        while (!d1 || !d2) {
            if (!d1) d1 = try_poll(p1, tg1, st1);
            if (!d2) d2 = try_poll(p2, tg2, st2);
        }
        __syncthreads();
        const float* h1v = hs + (p * 3 + 1) * HID;
        const float* h2v = hs + (p * 3 + 2) * HID;

        // B1: w_hh1 dots (packed), keep h1 packed
        unsigned long long af1 = 0ull, an1 = 0ull;
#pragma unroll
        for (int i = 0; i < 8; ++i) {
            ulonglong2 h2 = *(const ulonglong2*)&h1v[4 * (i * 32 + lane)];
            hu[i] = h2;
            af1 = ffma2(w1f[i].x, h2.x, af1); af1 = ffma2(w1f[i].y, h2.y, af1);
            an1 = ffma2(w1n[i].x, h2.x, an1); an1 = ffma2(w1n[i].y, h2.y, an1);
        }
        float accf1 = hsum2(af1), accn1 = hsum2(an1);
#pragma unroll
        for (int o = 16; o; o >>= 1) {
            accf1 += __shfl_xor_sync(0xffffffffu, accf1, o);
            accn1 += __shfl_xor_sync(0xffffffffu, accn1, o);
            g1fv  += __shfl_xor_sync(0xffffffffu, g1fv,  o);
            g1nv  += __shfl_xor_sync(0xffffffffu, g1nv,  o);
        }
        // publish h1(s)
        if (act1 && lane == 1) {
            float zf = g1fv + bi1f + accf1 + bh1f;
            zf = fminf(fmaxf(zf, -30.f), 30.f);
            float f = __fdividef(1.f, 1.f + __expf(-zf));
            float z = g1nv + bi1n + f * (accn1 + bh1n);
            z = fminf(fmaxf(z, -15.f), 15.f);
            float e = __expf(2.f * z);
            float n = 1.f - __fdividef(2.f, e + 1.f);
            float hy = n + (1.f - f) * (h1v[j] - n);
            st_tagged(pub1b + (p ? BUFW : 0), hy, (unsigned)s);
        }

        // B2: layer-2 gate dots from packed h1 (interleaved fp16)
        float g2fv = 0.f, g2nv = 0.f;
#pragma unroll
        for (int i = 0; i < 8; ++i) {
            uint4 wv = *(const uint4*)(r2w + (size_t)(i * 32 + lane) * 8);
            float2 f01 = __half22float2(*(const __half2*)&wv.x);
            float2 f23 = __half22float2(*(const __half2*)&wv.y);
            float2 n01 = __half22float2(*(const __half2*)&wv.z);
            float2 n23 = __half22float2(*(const __half2*)&wv.w);
            float h0f, h1f, h2f, h3f;
            UNPK(h0f, h1f, hu[i].x); UNPK(h2f, h3f, hu[i].y);
            g2fv += f01.x*h0f + f01.y*h1f + f23.x*h2f + f23.y*h3f;
            g2nv += n01.x*h0f + n01.y*h1f + n23.x*h2f + n23.y*h3f;
        }

        // C: w_hh2 dots (packed), weights streamed through L1
        unsigned long long af2 = 0ull, an2 = 0ull;
#pragma unroll
        for (int i = 0; i < 8; ++i) {
            int idx = i * 32 + lane;
            ulonglong2 h2 = *(const ulonglong2*)&h2v[4 * idx];
            ulonglong2 wa = w2f_p[idx];
            ulonglong2 wb = w2n_p[idx];
            af2 = ffma2(wa.x, h2.x, af2); af2 = ffma2(wa.y, h2.y, af2);
            an2 = ffma2(wb.x, h2.x, an2); an2 = ffma2(wb.y, h2.y, an2);
        }
        float accf2 = hsum2(af2), accn2 = hsum2(an2);
#pragma unroll
        for (int o = 16; o; o >>= 1) {
            accf2 += __shfl_xor_sync(0xffffffffu, accf2, o);
            accn2 += __shfl_xor_sync(0xffffffffu, accn2, o);
            g2fv  += __shfl_xor_sync(0xffffffffu, g2fv,  o);
            g2nv  += __shfl_xor_sync(0xffffffffu, g2nv,  o);
        }
        // publish h2(s-1) + layer-2 output
        if (act2 && lane == 2) {
            float zf = g2fv + bi2f + accf2 + bh2f;
            zf = fminf(fmaxf(zf, -30.f), 30.f);
            float f = __fdividef(1.f, 1.f + __expf(-zf));
            float z = g2nv + bi2n + f * (accn2 + bh2n);
            z = fminf(fmaxf(z, -15.f), 15.f);
            float e = __expf(2.f * z);
            float n = 1.f - __fdividef(2.f, e + 1.f);
            float hy = n + (1.f - f) * (h2v[j] - n);
            st_tagged(pub2b + (q ? BUFW : 0), hy, (unsigned)(s - 1));
            X2[(size_t)(s - 2) * HID + j] = hy;
        }
    }
}

// ---------------- final projection ----------------
__global__ void out_proj(const float* __restrict__ X, const float* __restrict__ w_out,
                         const float* __restrict__ b_out, float* __restrict__ out) {
    int gwarp = (blockIdx.x * blockDim.x + threadIdx.x) >> 5;
    int lane  = threadIdx.x & 31;
    if (gwarp >= T_SEQ) return;
    float acc = 0.f;
#pragma unroll
    for (int i = 0; i < HID / 32; ++i)
        acc += X[(size_t)gwarp * HID + i * 32 + lane] * w_out[i * 32 + lane];
#pragma unroll
    for (int off = 16; off; off >>= 1) acc += __shfl_down_sync(0xffffffffu, acc, off);
    if (lane == 0) out[gwarp] = acc + b_out[0];
}

// ---------------- host launcher ----------------
extern "C" void kernel_launch(void* const* d_in, const int* in_sizes, int n_in,
                              void* d_out, int out_size) {
    const float* S         = (const float*)d_in[0];
    const float* h0        = (const float*)d_in[1];
    const float* w_ih0     = (const float*)d_in[2];
    const float* w_hh0     = (const float*)d_in[3];
    const float* b_ih0     = (const float*)d_in[4];
    const float* b_hh0     = (const float*)d_in[5];
    const float* w_ih_rest = (const float*)d_in[6];
    const float* w_hh_rest = (const float*)d_in[7];
    const float* b_ih_rest = (const float*)d_in[8];
    const float* b_hh_rest = (const float*)d_in[9];
    const float* w_out     = (const float*)d_in[10];
    const float* b_out     = (const float*)d_in[11];
    float* out             = (float*)d_out;

    float *gi, *X2;
    cudaGetSymbolAddress((void**)&gi, g_gi);
    cudaGetSymbolAddress((void**)&X2, g_X2);

    const float* w_ih1 = w_ih_rest;
    const float* w_ih2 = w_ih_rest + (size_t)GDIM * HID;
    const float* b_ih1 = b_ih_rest;
    const float* b_ih2 = b_ih_rest + GDIM;
    const float* w_hh1 = w_hh_rest;
    const float* w_hh2 = w_hh_rest + (size_t)GDIM * HID;
    const float* b_hh1 = b_hh_rest;
    const float* b_hh2 = b_hh_rest + GDIM;

    const int smem_bytes = 32 * 1024 + 2 * 3 * 1024 * 4;   // 57344 (56 KB)
    cudaFuncSetAttribute(mgu_fused, cudaFuncAttributeMaxDynamicSharedMemorySize,
                         smem_bytes);

    init_all<<<1, 1024>>>(h0);
    gemm_bias_nt<<<dim3(GDIM / 128, T_SEQ / 128), 256>>>(S, w_ih0, b_ih0, gi,
                                                         T_SEQ, GDIM, 128);
    mgu_fused<<<NCTA, RECT, smem_bytes>>>(w_hh0, w_hh1, w_hh2,
                                          b_hh0, b_hh1, b_hh2,
                                          w_ih1, w_ih2, b_ih1, b_ih2,
                                          gi, X2);
    out_proj<<<T_SEQ * 32 / 256, 256>>>(X2, w_out, b_out, out);
}

// round 14
// speedup vs baseline: 1.5213x; 1.5213x over previous
#include <cuda_runtime.h>
#include <cuda_fp16.h>
#include <math.h>

#define T_SEQ 8192
#define HID   1024
#define GDIM  2048
#define NCTA  128
#define RECT  256            // 8 warps; warp w owns output cta*8+w for all 3 layers

// tagged hidden state, slice-spread: 4 tagged 8B words per 256B granule
#define GRPW 32                         // 8B words per 256B granule
#define BUFW (256 * GRPW)               // one buffer = 64 KB

// ---------------- static scratch (no allocation) ----------------
__device__ float g_gi[T_SEQ * GDIM];    // layer-0 input projection
__device__ float g_X2[T_SEQ * HID];     // layer-2 outputs
__device__ __align__(256) unsigned long long g_ht[3][2 * BUFW];

__device__ __forceinline__ size_t ht_idx(int word) {
    return (size_t)(word >> 2) * GRPW + (word & 3);
}
__device__ __forceinline__ void st_tagged(unsigned long long* p, float v, unsigned tag) {
    unsigned long long pk = ((unsigned long long)tag << 32) |
                            (unsigned long long)__float_as_uint(v);
    asm volatile("st.global.relaxed.gpu.b64 [%0], %1;" :: "l"(p), "l"(pk) : "memory");
}
#define LDV4(d0,d1,d2,d3,ptr) \
    asm volatile("ld.volatile.global.v4.b32 {%0,%1,%2,%3}, [%4];" \
                 : "=r"(d0),"=r"(d1),"=r"(d2),"=r"(d3) : "l"(ptr))

// packed 2xfp32 FMA (Blackwell f32x2 pipe)
__device__ __forceinline__ unsigned long long ffma2(unsigned long long a,
                                                    unsigned long long b,
                                                    unsigned long long c) {
    unsigned long long d;
    asm("fma.rn.f32x2 %0, %1, %2, %3;" : "=l"(d) : "l"(a), "l"(b), "l"(c));
    return d;
}
__device__ __forceinline__ float hsum2(unsigned long long v) {
    float lo, hi;
    asm("mov.b64 {%0, %1}, %2;" : "=f"(lo), "=f"(hi) : "l"(v));
    return lo + hi;
}
#define UNPK(lo, hi, u) \
    asm("mov.b64 {%0, %1}, %2;" : "=f"(lo), "=f"(hi) : "l"(u))

// try to accept this thread's granule (4 tagged words) for one h vector
__device__ __forceinline__ bool try4(const unsigned long long* p, unsigned tag,
                                     float* st) {
    unsigned a0,a1,a2,a3, b0,b1,b2,b3;
    LDV4(a0,a1,a2,a3, p); LDV4(b0,b1,b2,b3, p + 2);
    if (a1 == tag && a3 == tag && b1 == tag && b3 == tag) {
        st[0]=__uint_as_float(a0); st[1]=__uint_as_float(a2);
        st[2]=__uint_as_float(b0); st[3]=__uint_as_float(b2);
        return true;
    }
    return false;
}

// ---------------- init: seed all 3 layers' tagged h ----------------
__global__ void init_all(const float* __restrict__ h0) {
    int i = threadIdx.x;   // 1024 threads
#pragma unroll
    for (int l = 0; l < 3; ++l) {
        g_ht[l][ht_idx(i)] = (unsigned long long)__float_as_uint(h0[l * HID + i]);
        g_ht[l][BUFW + ht_idx(i)] = 0xFFFFFFFF00000000ull;
    }
}

// ---------------- C[M,N] = A[M,K] @ W[N,K]^T + bias[N] ----------------
__global__ __launch_bounds__(256, 2)
void gemm_bias_nt(const float* __restrict__ A, const float* __restrict__ W,
                  const float* __restrict__ bias, float* __restrict__ C,
                  int M, int N, int K) {
    __shared__ float As[8][128];
    __shared__ float Bs[8][128];
    const int tid  = threadIdx.x;
    const int bm   = blockIdx.y * 128;
    const int bn   = blockIdx.x * 128;
    const int lrow = tid >> 1;
    const int lcol = (tid & 1) << 2;
    const int ty   = tid >> 4;
    const int tx   = tid & 15;

    float acc[8][8];
#pragma unroll
    for (int i = 0; i < 8; ++i)
#pragma unroll
        for (int j = 0; j < 8; ++j) acc[i][j] = 0.f;

    const float* Aptr = A + (size_t)(bm + lrow) * K + lcol;
    const float* Wptr = W + (size_t)(bn + lrow) * K + lcol;

    for (int k0 = 0; k0 < K; k0 += 8) {
        float4 av = *(const float4*)(Aptr + k0);
        float4 wv = *(const float4*)(Wptr + k0);
        As[lcol + 0][lrow] = av.x; As[lcol + 1][lrow] = av.y;
        As[lcol + 2][lrow] = av.z; As[lcol + 3][lrow] = av.w;
        Bs[lcol + 0][lrow] = wv.x; Bs[lcol + 1][lrow] = wv.y;
        Bs[lcol + 2][lrow] = wv.z; Bs[lcol + 3][lrow] = wv.w;
        __syncthreads();
#pragma unroll
        for (int k = 0; k < 8; ++k) {
            float4 a0 = *(const float4*)&As[k][ty * 8];
            float4 a1 = *(const float4*)&As[k][ty * 8 + 4];
            float4 b0 = *(const float4*)&Bs[k][tx * 8];
            float4 b1 = *(const float4*)&Bs[k][tx * 8 + 4];
            float ar[8] = {a0.x, a0.y, a0.z, a0.w, a1.x, a1.y, a1.z, a1.w};
            float br[8] = {b0.x, b0.y, b0.z, b0.w, b1.x, b1.y, b1.z, b1.w};
#pragma unroll
            for (int i = 0; i < 8; ++i)
#pragma unroll
                for (int j = 0; j < 8; ++j) acc[i][j] += ar[i] * br[j];
        }
        __syncthreads();
    }

#pragma unroll
    for (int i = 0; i < 8; ++i) {
        int row = bm + ty * 8 + i;
#pragma unroll
        for (int j = 0; j < 8; j += 4) {
            float4 v;
            int col = bn + tx * 8 + j;
            v.x = acc[i][j + 0] + bias[col + 0];
            v.y = acc[i][j + 1] + bias[col + 1];
            v.z = acc[i][j + 2] + bias[col + 2];
            v.w = acc[i][j + 3] + bias[col + 3];
            *(float4*)&C[(size_t)row * N + col] = v;
        }
    }
}

// ---------------- fused 3-layer wavefront MGU (R12 + cross-step pre-poll) ----------------
// 128 CTAs x 256 threads, 1 CTA/SM. Warp w owns output j=cta*8+w of every layer.
// Wavefront step s: layer0 t=s, layer1 t=s-1, layer2 t=s-2.
// At step end, try-poll next step's h vectors once (they were published earlier
// in this step chip-wide), staging into the phase-q slots; carried flags make
// the next rendezvous usually free.
__global__ __launch_bounds__(RECT, 1)
void mgu_fused(const float* __restrict__ w_hh0, const float* __restrict__ w_hh1,
               const float* __restrict__ w_hh2,
               const float* __restrict__ b_hh0, const float* __restrict__ b_hh1,
               const float* __restrict__ b_hh2,
               const float* __restrict__ w_ih1, const float* __restrict__ w_ih2,
               const float* __restrict__ b_ih1, const float* __restrict__ b_ih2,
               const float* __restrict__ gi0, float* __restrict__ X2) {
    extern __shared__ char smraw[];
    __half* swi = (__half*)smraw;                    // [16][256][8] halves (64 KB)
    float*  hs  = (float*)(smraw + 64 * 1024);       // [2][3][1024] fp32 (24 KB)

    const int cta  = blockIdx.x;
    const int tid  = threadIdx.x;
    const int warp = tid >> 5;
    const int lane = tid & 31;
    const int j    = cta * 8 + warp;

    // ---- fill smem gate weights, fp16, f/n interleaved per 4-group ----
    for (int r = 0; r < 8; ++r) {
        int jr = cta * 8 + r;
        const float* f1 = w_ih1 + (size_t)jr * HID;
        const float* n1 = w_ih1 + (size_t)(HID + jr) * HID;
        const float* f2 = w_ih2 + (size_t)jr * HID;
        const float* n2 = w_ih2 + (size_t)(HID + jr) * HID;
        for (int k = tid; k < HID; k += RECT) {
            int g = k >> 2, pos = k & 3;
            size_t b0 = ((size_t)(0 * 8 + r) * 256 + g) * 8;
            size_t b1 = ((size_t)(8 + r) * 256 + g) * 8;
            swi[b0 + pos]     = __float2half(f1[k]);
            swi[b0 + 4 + pos] = __float2half(n1[k]);
            swi[b1 + pos]     = __float2half(f2[k]);
            swi[b1 + 4 + pos] = __float2half(n2[k]);
        }
    }

    // ---- w_hh rows for layers 0,1 as packed pairs ----
    ulonglong2 w0f[8], w0n[8], w1f[8], w1n[8];
#pragma unroll
    for (int i = 0; i < 8; ++i) {
        int col = 4 * (i * 32 + lane);
        w0f[i] = *(const ulonglong2*)&w_hh0[(size_t)j * HID + col];
        w0n[i] = *(const ulonglong2*)&w_hh0[(size_t)(HID + j) * HID + col];
        w1f[i] = *(const ulonglong2*)&w_hh1[(size_t)j * HID + col];
        w1n[i] = *(const ulonglong2*)&w_hh1[(size_t)(HID + j) * HID + col];
    }
    // layer-2 w_hh rows: stream through L1 (88 KB smem -> 140 KB carveout)
    const ulonglong2* w2f_p = (const ulonglong2*)(w_hh2 + (size_t)j * HID);
    const ulonglong2* w2n_p = (const ulonglong2*)(w_hh2 + (size_t)(HID + j) * HID);

    const float bh0f = b_hh0[j], bh0n = b_hh0[HID + j];
    const float bi1f = b_ih1[j], bi1n = b_ih1[HID + j];
    const float bh1f = b_hh1[j], bh1n = b_hh1[HID + j];
    const float bi2f = b_ih2[j], bi2n = b_ih2[HID + j];
    const float bh2f = b_hh2[j], bh2n = b_hh2[HID + j];

    const __half* r1w = swi + (size_t)(0 * 8 + warp) * 256 * 8;
    const __half* r2w = swi + (size_t)(8 + warp) * 256 * 8;

    // hoisted poll bases (per-thread granule) and publish slots (per-warp)
    const unsigned long long* b0p = g_ht[0] + (size_t)tid * GRPW;
    const unsigned long long* b1p = g_ht[1] + (size_t)tid * GRPW;
    const unsigned long long* b2p = g_ht[2] + (size_t)tid * GRPW;
    unsigned long long* pub0b = g_ht[0] + ht_idx(j);
    unsigned long long* pub1b = g_ht[1] + ht_idx(j);
    unsigned long long* pub2b = g_ht[2] + ht_idx(j);

    __syncthreads();

    // gi prefetch pipeline: hold step-s values, prefetch s+1 during step s
    float gif0 = 0.f, gin0 = 0.f;
    if (lane == 0) {
        gif0 = __ldcg(&gi0[j]);
        gin0 = __ldcg(&gi0[HID + j]);
    }

    bool pre0 = false, pre1 = false, pre2 = false;   // carried pre-staged flags

    for (int s = 0; s < T_SEQ + 2; ++s) {
        const int p = s & 1, q = p ^ 1;
        const bool act0 = s < T_SEQ;
        const bool act1 = (s >= 1) & (s <= T_SEQ);
        const bool act2 = s >= 2;

        const unsigned long long* p0 = b0p + (p ? BUFW : 0);
        const unsigned long long* p1 = b1p + (q ? BUFW : 0);
        const unsigned long long* p2 = b2p + (p ? BUFW : 0);
        const unsigned tg0 = (unsigned)s, tg1 = (unsigned)(s - 1), tg2 = (unsigned)(s - 2);
        bool d0 = !(s <= T_SEQ) || pre0;
        bool d1 = !(s >= 1)     || pre1;
        bool d2 = !(s >= 2)     || pre2;
        float* st0 = hs + (p * 3 + 0) * HID + 4 * tid;
        float* st1 = hs + (p * 3 + 1) * HID + 4 * tid;
        float* st2 = hs + (p * 3 + 2) * HID + 4 * tid;

        // ======== rendezvous 1: h0 (drain h1/h2 opportunistically) ========
        if (!d1) d1 = try4(p1, tg1, st1);
        if (!d2) d2 = try4(p2, tg2, st2);
        while (!d0) {
            d0 = try4(p0, tg0, st0);
            if (!d1) d1 = try4(p1, tg1, st1);
            if (!d2) d2 = try4(p2, tg2, st2);
        }
        __syncthreads();
        const float* h0v = hs + (p * 3 + 0) * HID;

        // A1: w_hh0 dots (packed FMA), keep h0 packed in registers
        ulonglong2 hu[8];
        unsigned long long af0 = 0ull, an0 = 0ull;
#pragma unroll
        for (int i = 0; i < 8; ++i) {
            ulonglong2 h2 = *(const ulonglong2*)&h0v[4 * (i * 32 + lane)];
            hu[i] = h2;
            af0 = ffma2(w0f[i].x, h2.x, af0); af0 = ffma2(w0f[i].y, h2.y, af0);
            an0 = ffma2(w0n[i].x, h2.x, an0); an0 = ffma2(w0n[i].y, h2.y, an0);
        }
        float accf0 = hsum2(af0), accn0 = hsum2(an0);
#pragma unroll
        for (int o = 16; o; o >>= 1) {
            accf0 += __shfl_xor_sync(0xffffffffu, accf0, o);
            accn0 += __shfl_xor_sync(0xffffffffu, accn0, o);
        }
        // publish h0(s+1) EARLY
        if (act0 && lane == 0) {
            float zf = gif0 + accf0 + bh0f;
            zf = fminf(fmaxf(zf, -30.f), 30.f);
            float f = __fdividef(1.f, 1.f + __expf(-zf));
            float z = gin0 + f * (accn0 + bh0n);
            z = fminf(fmaxf(z, -15.f), 15.f);
            float e = __expf(2.f * z);
            float n = 1.f - __fdividef(2.f, e + 1.f);
            float hy = n + (1.f - f) * (h0v[j] - n);
            st_tagged(pub0b + (q ? BUFW : 0), hy, (unsigned)(s + 1));
        }
        if (s + 1 < T_SEQ && lane == 0) {
            gif0 = __ldcg(&gi0[(size_t)(s + 1) * GDIM + j]);
            gin0 = __ldcg(&gi0[(size_t)(s + 1) * GDIM + HID + j]);
        }

        // A2: layer-1 gate dots (interleaved fp16, one LDS.128/iter)
        float g1fv = 0.f, g1nv = 0.f;
#pragma unroll
        for (int i = 0; i < 8; ++i) {
            uint4 wv = *(const uint4*)(r1w + (size_t)(i * 32 + lane) * 8);
            float2 f01 = __half22float2(*(const __half2*)&wv.x);
            float2 f23 = __half22float2(*(const __half2*)&wv.y);
            float2 n01 = __half22float2(*(const __half2*)&wv.z);
            float2 n23 = __half22float2(*(const __half2*)&wv.w);
            float h0f, h1f, h2f, h3f;
            UNPK(h0f, h1f, hu[i].x); UNPK(h2f, h3f, hu[i].y);
            g1fv += f01.x*h0f + f01.y*h1f + f23.x*h2f + f23.y*h3f;
            g1nv += n01.x*h0f + n01.y*h1f + n23.x*h2f + n23.y*h3f;
        }

        // ======== rendezvous 2: h1 AND h2 together ========
        while (!d1 || !d2) {
            if (!d1) d1 = try4(p1, tg1, st1);
            if (!d2) d2 = try4(p2, tg2, st2);
        }
        __syncthreads();
        const float* h1v = hs + (p * 3 + 1) * HID;
        const float* h2v = hs + (p * 3 + 2) * HID;

        // B1: w_hh1 dots (packed), keep h1 packed
        unsigned long long af1 = 0ull, an1 = 0ull;
#pragma unroll
        for (int i = 0; i < 8; ++i) {
            ulonglong2 h2 = *(const ulonglong2*)&h1v[4 * (i * 32 + lane)];
            hu[i] = h2;
            af1 = ffma2(w1f[i].x, h2.x, af1); af1 = ffma2(w1f[i].y, h2.y, af1);
            an1 = ffma2(w1n[i].x, h2.x, an1); an1 = ffma2(w1n[i].y, h2.y, an1);
        }
        float accf1 = hsum2(af1), accn1 = hsum2(an1);
#pragma unroll
        for (int o = 16; o; o >>= 1) {
            accf1 += __shfl_xor_sync(0xffffffffu, accf1, o);
            accn1 += __shfl_xor_sync(0xffffffffu, accn1, o);
            g1fv  += __shfl_xor_sync(0xffffffffu, g1fv,  o);
            g1nv  += __shfl_xor_sync(0xffffffffu, g1nv,  o);
        }
        // publish h1(s)
        if (act1 && lane == 1) {
            float zf = g1fv + bi1f + accf1 + bh1f;
            zf = fminf(fmaxf(zf, -30.f), 30.f);
            float f = __fdividef(1.f, 1.f + __expf(-zf));
            float z = g1nv + bi1n + f * (accn1 + bh1n);
            z = fminf(fmaxf(z, -15.f), 15.f);
            float e = __expf(2.f * z);
            float n = 1.f - __fdividef(2.f, e + 1.f);
            float hy = n + (1.f - f) * (h1v[j] - n);
            st_tagged(pub1b + (p ? BUFW : 0), hy, (unsigned)s);
        }

        // B2: layer-2 gate dots from packed h1 (interleaved fp16)
        float g2fv = 0.f, g2nv = 0.f;
#pragma unroll
        for (int i = 0; i < 8; ++i) {
            uint4 wv = *(const uint4*)(r2w + (size_t)(i * 32 + lane) * 8);
            float2 f01 = __half22float2(*(const __half2*)&wv.x);
            float2 f23 = __half22float2(*(const __half2*)&wv.y);
            float2 n01 = __half22float2(*(const __half2*)&wv.z);
            float2 n23 = __half22float2(*(const __half2*)&wv.w);
            float h0f, h1f, h2f, h3f;
            UNPK(h0f, h1f, hu[i].x); UNPK(h2f, h3f, hu[i].y);
            g2fv += f01.x*h0f + f01.y*h1f + f23.x*h2f + f23.y*h3f;
            g2nv += n01.x*h0f + n01.y*h1f + n23.x*h2f + n23.y*h3f;
        }

        // C: w_hh2 dots (packed), weights streamed through L1
        unsigned long long af2 = 0ull, an2 = 0ull;
#pragma unroll
        for (int i = 0; i < 8; ++i) {
            int idx = i * 32 + lane;
            ulonglong2 h2 = *(const ulonglong2*)&h2v[4 * idx];
            ulonglong2 wa = w2f_p[idx];
            ulonglong2 wb = w2n_p[idx];
            af2 = ffma2(wa.x, h2.x, af2); af2 = ffma2(wa.y, h2.y, af2);
            an2 = ffma2(wb.x, h2.x, an2); an2 = ffma2(wb.y, h2.y, an2);
        }
        float accf2 = hsum2(af2), accn2 = hsum2(an2);
#pragma unroll
        for (int o = 16; o; o >>= 1) {
            accf2 += __shfl_xor_sync(0xffffffffu, accf2, o);
            accn2 += __shfl_xor_sync(0xffffffffu, accn2, o);
            g2fv  += __shfl_xor_sync(0xffffffffu, g2fv,  o);
            g2nv  += __shfl_xor_sync(0xffffffffu, g2nv,  o);
        }
        // publish h2(s-1) + layer-2 output
        if (act2 && lane == 2) {
            float zf = g2fv + bi2f + accf2 + bh2f;
            zf = fminf(fmaxf(zf, -30.f), 30.f);
            float f = __fdividef(1.f, 1.f + __expf(-zf));
            float z = g2nv + bi2n + f * (accn2 + bh2n);
            z = fminf(fmaxf(z, -15.f), 15.f);
            float e = __expf(2.f * z);
            float n = 1.f - __fdividef(2.f, e + 1.f);
            float hy = n + (1.f - f) * (h2v[j] - n);
            st_tagged(pub2b + (q ? BUFW : 0), hy, (unsigned)(s - 1));
            X2[(size_t)(s - 2) * HID + j] = hy;
        }

        // ======== cross-step pre-poll: stage next step's vectors into phase q ====
        // (phase-q slots were last read in step s-1; all warps are past this
        //  step's barriers, so staging writes are race-free. Visibility to other
        //  warps is provided by step s+1's rendezvous-1 __syncthreads.)
        pre0 = pre1 = pre2 = false;
        if (s + 1 < T_SEQ + 2) {
            if (s + 1 <= T_SEQ)
                pre0 = try4(b0p + (q ? BUFW : 0), (unsigned)(s + 1),
                            hs + (q * 3 + 0) * HID + 4 * tid);
            pre1 = try4(b1p + (p ? BUFW : 0), (unsigned)s,
                        hs + (q * 3 + 1) * HID + 4 * tid);
            if (s + 1 >= 2)
                pre2 = try4(b2p + (q ? BUFW : 0), (unsigned)(s - 1),
                            hs + (q * 3 + 2) * HID + 4 * tid);
        }
    }
}

// ---------------- final projection ----------------
__global__ void out_proj(const float* __restrict__ X, const float* __restrict__ w_out,
                         const float* __restrict__ b_out, float* __restrict__ out) {
    int gwarp = (blockIdx.x * blockDim.x + threadIdx.x) >> 5;
    int lane  = threadIdx.x & 31;
    if (gwarp >= T_SEQ) return;
    float acc = 0.f;
#pragma unroll
    for (int i = 0; i < HID / 32; ++i)
        acc += X[(size_t)gwarp * HID + i * 32 + lane] * w_out[i * 32 + lane];
#pragma unroll
    for (int off = 16; off; off >>= 1) acc += __shfl_down_sync(0xffffffffu, acc, off);
    if (lane == 0) out[gwarp] = acc + b_out[0];
}

// ---------------- host launcher ----------------
extern "C" void kernel_launch(void* const* d_in, const int* in_sizes, int n_in,
                              void* d_out, int out_size) {
    const float* S         = (const float*)d_in[0];
    const float* h0        = (const float*)d_in[1];
    const float* w_ih0     = (const float*)d_in[2];
    const float* w_hh0     = (const float*)d_in[3];
    const float* b_ih0     = (const float*)d_in[4];
    const float* b_hh0     = (const float*)d_in[5];
    const float* w_ih_rest = (const float*)d_in[6];
    const float* w_hh_rest = (const float*)d_in[7];
    const float* b_ih_rest = (const float*)d_in[8];
    const float* b_hh_rest = (const float*)d_in[9];
    const float* w_out     = (const float*)d_in[10];
    const float* b_out     = (const float*)d_in[11];
    float* out             = (float*)d_out;

    float *gi, *X2;
    cudaGetSymbolAddress((void**)&gi, g_gi);
    cudaGetSymbolAddress((void**)&X2, g_X2);

    const float* w_ih1 = w_ih_rest;
    const float* w_ih2 = w_ih_rest + (size_t)GDIM * HID;
    const float* b_ih1 = b_ih_rest;
    const float* b_ih2 = b_ih_rest + GDIM;
    const float* w_hh1 = w_hh_rest;
    const float* w_hh2 = w_hh_rest + (size_t)GDIM * HID;
    const float* b_hh1 = b_hh_rest;
    const float* b_hh2 = b_hh_rest + GDIM;

    const int smem_bytes = 64 * 1024 + 2 * 3 * 1024 * 4;   // 90112 (88 KB)
    cudaFuncSetAttribute(mgu_fused, cudaFuncAttributeMaxDynamicSharedMemorySize,
                         smem_bytes);

    init_all<<<1, 1024>>>(h0);
    gemm_bias_nt<<<dim3(GDIM / 128, T_SEQ / 128), 256>>>(S, w_ih0, b_ih0, gi,
                                                         T_SEQ, GDIM, 128);
    mgu_fused<<<NCTA, RECT, smem_bytes>>>(w_hh0, w_hh1, w_hh2,
                                          b_hh0, b_hh1, b_hh2,
                                          w_ih1, w_ih2, b_ih1, b_ih2,
                                          gi, X2);
    out_proj<<<T_SEQ * 32 / 256, 256>>>(X2, w_out, b_out, out);
}